// round 6
// baseline (speedup 1.0000x reference)
#include <cuda_runtime.h>
#include <math.h>

#define Bc 4
#define Nc 1024
#define Hc 8
#define Dc 64
#define BSc 32
#define NBc 32
#define STOP 16
#define SCALE 0.125f

typedef unsigned long long u64;

__device__ float g_kcmp[Bc*NBc*Hc*Dc];
__device__ float g_vcmp[Bc*NBc*Hc*Dc];

__device__ __forceinline__ float siluf(float s) {
    return s / (1.f + __expf(-s));
}
__device__ __forceinline__ u64 ffma2(u64 a, u64 b, u64 c) {
    u64 d;
    asm("fma.rn.f32x2 %0, %1, %2, %3;" : "=l"(d) : "l"(a), "l"(b), "l"(c));
    return d;
}
__device__ __forceinline__ u64 dup2(float x) {
    u64 r;
    asm("mov.b64 %0, {%1, %1};" : "=l"(r) : "f"(x));
    return r;
}
__device__ __forceinline__ float2 u2f2(u64 u) {
    float2 f;
    asm("mov.b64 {%0, %1}, %2;" : "=f"(f.x), "=f"(f.y) : "l"(u));
    return f;
}
__device__ __forceinline__ void cpa16(unsigned dst, const void* src) {
    asm volatile("cp.async.cg.shared.global [%0], [%1], 16;" :: "r"(dst), "l"(src) : "memory");
}
#define CP_COMMIT() asm volatile("cp.async.commit_group;" ::: "memory")
#define CP_WAIT(n)  asm volatile("cp.async.wait_group %0;" :: "n"(n) : "memory")

#define SMEM_Q   0
#define SMEM_K0  8192
#define SMEM_K1  24576
#define SMEM_V0  40960
#define SMEM_V1  57344
#define SMEM_P   73728
#define SMEM_TOT 81920

__global__ void meanKV(const float* __restrict__ pk, const float* __restrict__ pv) {
    int blk = blockIdx.x;
    int b  = blk / (NBc*Hc);
    int kb = (blk / Hc) % NBc;
    int h  = blk % Hc;
    int d  = threadIdx.x;
    float sk = 0.f, sv = 0.f;
    int base = ((b*Nc + kb*BSc)*Hc + h)*Dc + d;
    #pragma unroll 8
    for (int j = 0; j < BSc; j++) {
        sk += pk[base + j*Hc*Dc];
        sv += pv[base + j*Hc*Dc];
    }
    int o = ((b*NBc + kb)*Hc + h)*Dc + d;
    g_kcmp[o] = sk * (1.f/BSc);
    g_vcmp[o] = sv * (1.f/BSc);
}

// CTA = (q_block, head, batch); 8 warps; warp w owns rows {w,w+8,w+16,w+24}.
// Phase B: paired 64-key tiles, 2-stage cp.async pipeline, p stored duplicated.
__global__ __launch_bounds__(256, 2) void hstu_main(
    const float* __restrict__ pq, const float* __restrict__ pk,
    const float* __restrict__ pvv, const float* __restrict__ gate_w,
    const int* __restrict__ xoff, float* __restrict__ out)
{
    extern __shared__ __align__(16) char smem_raw[];
    float4* qsh4  = (float4*)(smem_raw + SMEM_Q);    // [32*16]
    u64*    psh64 = (u64*)  (smem_raw + SMEM_P);     // [32*32] p duplicated
    float4* kbSp[2] = {(float4*)(smem_raw + SMEM_K0), (float4*)(smem_raw + SMEM_K1)};
    float4* vbSp[2] = {(float4*)(smem_raw + SMEM_V0), (float4*)(smem_raw + SMEM_V1)};
    __shared__ int list[33];
    __shared__ int lcnt;
    __shared__ unsigned unionm;

    int qb = (NBc - 1) - blockIdx.x;   // heavy first
    int h = blockIdx.y, b = blockIdx.z;
    int len = xoff[b+1] - xoff[b];
    if (qb * BSc >= len) return;
    int nvalid = len - qb*BSc; if (nvalid > BSc) nvalid = BSc;
    int t0 = xoff[b];
    int tid = threadIdx.x, lane = tid & 31, w = tid >> 5;

    unsigned sbase = (unsigned)__cvta_generic_to_shared(smem_raw);
    unsigned qbase = sbase + SMEM_Q;
    unsigned kbase[2] = {sbase + SMEM_K0, sbase + SMEM_K1};
    unsigned vbase[2] = {sbase + SMEM_V0, sbase + SMEM_V1};

    const ulonglong2* qshU = (const ulonglong2*)qsh4;

    // ---- Phase A staging: q + compressed K/V into stage 0 ----
    {
        int r0 = tid >> 4, c4 = tid & 15;
        #pragma unroll
        for (int step = 0; step < 2; step++) {
            int row = r0 + step*16;
            cpa16(qbase + (unsigned)(row*16 + c4)*16u,
                  pq + ((b*Nc + qb*BSc + row)*Hc + h)*Dc + c4*4);
            int gc = ((b*NBc + row)*Hc + h)*Dc + c4*4;
            cpa16(kbase[0] + (unsigned)(c4*64 + (row ^ c4))*16u, g_kcmp + gc);
            cpa16(vbase[0] + (unsigned)(row*16 + c4)*16u,        g_vcmp + gc);
        }
    }
    CP_COMMIT();
    if (tid == 0) unionm = 0;
    CP_WAIT(0);
    __syncthreads();

    u64 accC[4] = {0,0,0,0}, accS[4] = {0,0,0,0};
    unsigned mysel[4];

    // ================= Phase A =================
    {
        const ulonglong2* kbU = (const ulonglong2*)kbSp[0];
        const u64*        vbU = (const u64*)vbSp[0];
        u64 sa[4] = {0,0,0,0};
        #pragma unroll
        for (int d4 = 0; d4 < 16; d4++) {
            ulonglong2 k0 = kbU[d4*64 + (lane ^ d4)];
            #pragma unroll
            for (int qi = 0; qi < 4; qi++) {
                ulonglong2 q = qshU[(w + qi*8)*16 + d4];
                sa[qi] = ffma2(q.x, k0.x, sa[qi]);
                sa[qi] = ffma2(q.y, k0.y, sa[qi]);
            }
        }
        bool causal = (lane <= qb);
        #pragma unroll
        for (int qi = 0; qi < 4; qi++) {
            int r = w + qi*8;
            float2 fa = u2f2(sa[qi]);
            float sc = (fa.x + fa.y) * SCALE;
            bool rowok = (r < nvalid);
            psh64[r*32 + lane] = dup2((causal && rowok) ? siluf(sc) : 0.f);

            unsigned sel;
            if (!rowok) {
                sel = 0u;
            } else if (qb < STOP) {
                sel = (1u << (qb + 1)) - 1u;
            } else {
                unsigned ub = __float_as_uint(sc);
                unsigned u = ((int)ub < 0) ? ~ub : (ub | 0x80000000u);
                if (!causal) u = 0u;
                unsigned T = 0u;
                #pragma unroll
                for (int bit = 31; bit >= 0; --bit) {
                    unsigned cand = T | (1u << bit);
                    unsigned bal = __ballot_sync(0xffffffffu, u >= cand);
                    if (__popc(bal) >= STOP) T = cand;
                }
                unsigned gt = __ballot_sync(0xffffffffu, u > T);
                unsigned eq = __ballot_sync(0xffffffffu, u == T);
                int need = STOP - __popc(gt);
                bool take = ((eq >> lane) & 1u) &&
                            (__popc(eq & ((1u << lane) - 1u)) < need);
                unsigned eqt = __ballot_sync(0xffffffffu, take);
                sel = gt | eqt;
            }
            mysel[qi] = sel;
        }
        __syncwarp();
        unsigned wsel0 = mysel[0] | mysel[1] | mysel[2] | mysel[3];
        if (lane == 0) atomicOr(&unionm, wsel0);

        // compressed PV (keys 0..qb), p pre-duplicated
        int j2hi = qb >> 1;
        for (int j2 = 0; j2 <= j2hi; j2++) {
            u64 v0 = vbU[(2*j2)*32 + lane];
            u64 v1 = vbU[(2*j2 + 1)*32 + lane];
            #pragma unroll
            for (int qi = 0; qi < 4; qi++) {
                ulonglong2 pp = *(const ulonglong2*)&psh64[(w + qi*8)*32 + 2*j2];
                accC[qi] = ffma2(pp.x, v0, accC[qi]);
                accC[qi] = ffma2(pp.y, v1, accC[qi]);
            }
        }
    }
    unsigned wsel = mysel[0] | mysel[1] | mysel[2] | mysel[3];
    __syncthreads();
    unsigned um = unionm;
    if (tid == 0) {
        int c = 0;
        for (int kb = 0; kb <= qb; kb++)
            if ((um >> kb) & 1u) list[c++] = kb;
        lcnt = c;
    }
    __syncthreads();
    int cnt = lcnt;
    int np = (cnt + 1) >> 1;

    // issue one 64-key pair into stage s
    auto issue_pair = [&](int ip, int s) {
        int i0 = ip*2;
        int kb0 = list[i0];
        int kb1 = list[(i0 + 1 < cnt) ? i0 + 1 : i0];
        int r0 = tid >> 4, c4 = tid & 15;
        #pragma unroll
        for (int step = 0; step < 2; step++) {
            int row = r0 + step*16;
            int g0 = ((b*Nc + kb0*BSc + row)*Hc + h)*Dc + c4*4;
            int g1 = ((b*Nc + kb1*BSc + row)*Hc + h)*Dc + c4*4;
            cpa16(kbase[s] + (unsigned)(c4*64 + (row ^ c4))*16u,        pk + g0);
            cpa16(kbase[s] + (unsigned)(c4*64 + ((row + 32) ^ c4))*16u, pk + g1);
            cpa16(vbase[s] + (unsigned)(row*16 + c4)*16u,        pvv + g0);
            cpa16(vbase[s] + (unsigned)((row + 32)*16 + c4)*16u, pvv + g1);
        }
        CP_COMMIT();
    };

    // ================= Phase B: 2-stage pipeline over pairs =================
    if (np > 0) issue_pair(0, 0);
    if (np > 1) issue_pair(1, 1);

    for (int ip = 0; ip < np; ip++) {
        if (ip + 1 < np) { CP_WAIT(1); } else { CP_WAIT(0); }
        __syncthreads();
        int s = ip & 1;
        int kb0 = list[ip*2];
        bool has1 = (ip*2 + 1 < cnt);
        int kb1 = has1 ? list[ip*2 + 1] : kb0;
        bool need0 = (wsel >> kb0) & 1u;
        bool need1 = has1 && ((wsel >> kb1) & 1u);

        if (need0 | need1) {
            const ulonglong2* kbU = (const ulonglong2*)kbSp[s];
            const u64*        vbU = (const u64*)vbSp[s];
            u64 s0[4] = {0,0,0,0}, s1[4] = {0,0,0,0};
            #pragma unroll
            for (int d4 = 0; d4 < 16; d4++) {
                ulonglong2 k0 = kbU[d4*64 + (lane ^ d4)];
                ulonglong2 k1 = kbU[d4*64 + ((lane + 32) ^ d4)];
                #pragma unroll
                for (int qi = 0; qi < 4; qi++) {
                    ulonglong2 q = qshU[(w + qi*8)*16 + d4];
                    s0[qi] = ffma2(q.x, k0.x, s0[qi]);
                    s0[qi] = ffma2(q.y, k0.y, s0[qi]);
                    s1[qi] = ffma2(q.x, k1.x, s1[qi]);
                    s1[qi] = ffma2(q.y, k1.y, s1[qi]);
                }
            }
            // ---- tile 0 ----
            if (need0) {
                #pragma unroll
                for (int qi = 0; qi < 4; qi++) {
                    int r = w + qi*8;
                    int jmax = (kb0 == qb) ? r : 31;
                    bool u0 = ((mysel[qi] >> kb0) & 1u) && (lane <= jmax);
                    float2 f0 = u2f2(s0[qi]);
                    psh64[r*32 + lane] = dup2(u0 ? siluf((f0.x + f0.y)*SCALE) : 0.f);
                }
                __syncwarp();
                #pragma unroll
                for (int j2 = 0; j2 < 16; j2++) {
                    u64 v0 = vbU[(2*j2)*32 + lane];
                    u64 v1 = vbU[(2*j2 + 1)*32 + lane];
                    #pragma unroll
                    for (int qi = 0; qi < 4; qi++) {
                        ulonglong2 pp = *(const ulonglong2*)&psh64[(w + qi*8)*32 + 2*j2];
                        accS[qi] = ffma2(pp.x, v0, accS[qi]);
                        accS[qi] = ffma2(pp.y, v1, accS[qi]);
                    }
                }
                __syncwarp();
            }
            // ---- tile 1 ----
            if (need1) {
                #pragma unroll
                for (int qi = 0; qi < 4; qi++) {
                    int r = w + qi*8;
                    int jmax = (kb1 == qb) ? r : 31;
                    bool u1 = ((mysel[qi] >> kb1) & 1u) && (lane <= jmax);
                    float2 f1 = u2f2(s1[qi]);
                    psh64[r*32 + lane] = dup2(u1 ? siluf((f1.x + f1.y)*SCALE) : 0.f);
                }
                __syncwarp();
                #pragma unroll
                for (int j2 = 0; j2 < 16; j2++) {
                    u64 v0 = vbU[(32 + 2*j2)*32 + lane];
                    u64 v1 = vbU[(32 + 2*j2 + 1)*32 + lane];
                    #pragma unroll
                    for (int qi = 0; qi < 4; qi++) {
                        ulonglong2 pp = *(const ulonglong2*)&psh64[(w + qi*8)*32 + 2*j2];
                        accS[qi] = ffma2(pp.x, v0, accS[qi]);
                        accS[qi] = ffma2(pp.y, v1, accS[qi]);
                    }
                }
            }
        }
        __syncthreads();
        if (ip + 2 < np) issue_pair(ip + 2, s);
    }

    // ================= Output + gates (epilogue) =================
    const float* qs = (const float*)qsh4;
    const float* gw = gate_w + h*Dc*3;
    #pragma unroll
    for (int qi = 0; qi < 4; qi++) {
        int r = w + qi*8;
        if (r >= nvalid) continue;   // warp-uniform
        float q0 = qs[r*64 + 2*lane], q1 = qs[r*64 + 2*lane + 1];
        float pg0 = q0*gw[(2*lane)*3 + 0] + q1*gw[(2*lane+1)*3 + 0];
        float pg1 = q0*gw[(2*lane)*3 + 1] + q1*gw[(2*lane+1)*3 + 1];
        #pragma unroll
        for (int off = 16; off > 0; off >>= 1) {
            pg0 += __shfl_xor_sync(0xffffffffu, pg0, off);
            pg1 += __shfl_xor_sync(0xffffffffu, pg1, off);
        }
        float gcv = 1.f / (1.f + __expf(-pg0));
        float gsv = 1.f / (1.f + __expf(-pg1));
        float2 c = u2f2(accC[qi]), s2 = u2f2(accS[qi]);
        int n = qb*BSc + r;
        int o = ((t0 + n)*Hc + h)*Dc;
        float2 o2;
        o2.x = c.x*gcv + s2.x*gsv;
        o2.y = c.y*gcv + s2.y*gsv;
        *((float2*)(out + o) + lane) = o2;
    }
}

extern "C" void kernel_launch(void* const* d_in, const int* in_sizes, int n_in,
                              void* d_out, int out_size) {
    const float* pq   = (const float*)d_in[4];
    const float* pk   = (const float*)d_in[5];
    const float* pv   = (const float*)d_in[6];
    const int*   xoff = (const int*)d_in[7];
    const float* gw   = (const float*)d_in[8];
    float* out = (float*)d_out;

    static int configured = 0;
    if (!configured) {
        cudaFuncSetAttribute(hstu_main,
                             cudaFuncAttributeMaxDynamicSharedMemorySize, SMEM_TOT);
        configured = 1;
    }

    meanKV<<<Bc*NBc*Hc, 64>>>(pk, pv);
    dim3 grid(NBc, Hc, Bc);
    hstu_main<<<grid, 256, SMEM_TOT>>>(pq, pk, pv, gw, xoff, out);
}

// round 7
// speedup vs baseline: 1.3651x; 1.3651x over previous
#include <cuda_runtime.h>
#include <math.h>

#define Bc 4
#define Nc 1024
#define Hc 8
#define Dc 64
#define BSc 32
#define NBc 32
#define STOP 16
#define SCALE 0.125f

typedef unsigned long long u64;

__device__ float g_kcmp[Bc*NBc*Hc*Dc];
__device__ float g_vcmp[Bc*NBc*Hc*Dc];

__device__ __forceinline__ float siluf(float s) {
    return s / (1.f + __expf(-s));
}
__device__ __forceinline__ u64 ffma2(u64 a, u64 b, u64 c) {
    u64 d;
    asm("fma.rn.f32x2 %0, %1, %2, %3;" : "=l"(d) : "l"(a), "l"(b), "l"(c));
    return d;
}
__device__ __forceinline__ u64 dup2(float x) {
    u64 r;
    asm("mov.b64 %0, {%1, %1};" : "=l"(r) : "f"(x));
    return r;
}
__device__ __forceinline__ float2 u2f2(u64 u) {
    float2 f;
    asm("mov.b64 {%0, %1}, %2;" : "=f"(f.x), "=f"(f.y) : "l"(u));
    return f;
}

__global__ void meanKV(const float* __restrict__ pk, const float* __restrict__ pv) {
    int blk = blockIdx.x;
    int b  = blk / (NBc*Hc);
    int kb = (blk / Hc) % NBc;
    int h  = blk % Hc;
    int d  = threadIdx.x;
    float sk = 0.f, sv = 0.f;
    int base = ((b*Nc + kb*BSc)*Hc + h)*Dc + d;
    #pragma unroll 8
    for (int j = 0; j < BSc; j++) {
        sk += pk[base + j*Hc*Dc];
        sv += pv[base + j*Hc*Dc];
    }
    int o = ((b*NBc + kb)*Hc + h)*Dc + d;
    g_kcmp[o] = sk * (1.f/BSc);
    g_vcmp[o] = sv * (1.f/BSc);
}

// CTA = (q_block, head, batch); 4 warps; warp w owns query rows {w+4*qi}, qi=0..7.
// Phase B: paired 64-key tiles (LDG->STS staging).
__global__ __launch_bounds__(128, 4) void hstu_main(
    const float* __restrict__ pq, const float* __restrict__ pk,
    const float* __restrict__ pvv, const float* __restrict__ gate_w,
    const int* __restrict__ xoff, float* __restrict__ out)
{
    __shared__ __align__(16) float4 qsh4[32*16];   // 8KB
    __shared__ __align__(16) float4 kb4[16*64];    // 16KB K swizzled [d4][key^d4] (pair)
    __shared__ __align__(16) float4 vb4[64*16];    // 16KB V [key][d4] (pair)
    __shared__ __align__(16) float  p_sh[32*32];   // 4KB p[row][key]
    __shared__ int list[33];
    __shared__ int lcnt;
    __shared__ unsigned unionm;

    int qb = (NBc - 1) - blockIdx.x;   // heavy first
    int h = blockIdx.y, b = blockIdx.z;
    int len = xoff[b+1] - xoff[b];
    if (qb * BSc >= len) return;
    int nvalid = len - qb*BSc; if (nvalid > BSc) nvalid = BSc;
    int t0 = xoff[b];
    int tid = threadIdx.x, lane = tid & 31, w = tid >> 5;

    const ulonglong2* qshU = (const ulonglong2*)qsh4;
    const ulonglong2* kbU  = (const ulonglong2*)kb4;
    const u64*        vbU  = (const u64*)vb4;
    const float4*     p4   = (const float4*)p_sh;

    // ---- stage q + compressed K/V (keys 0..31 of pair buffers) ----
    #pragma unroll
    for (int i = tid; i < 512; i += 128) {
        int r = i >> 4, c4 = i & 15;
        qsh4[r*16 + c4] = ((const float4*)(pq + ((b*Nc + qb*BSc + r)*Hc + h)*Dc))[c4];
        int gc = ((b*NBc + r)*Hc + h)*Dc;
        kb4[c4*64 + (r ^ c4)] = ((const float4*)(g_kcmp + gc))[c4];
        vb4[r*16 + c4]        = ((const float4*)(g_vcmp + gc))[c4];
    }
    if (tid == 0) unionm = 0;
    __syncthreads();

    u64 accC[8] = {0,0,0,0,0,0,0,0}, accS[8] = {0,0,0,0,0,0,0,0};
    unsigned mysel[8];

    // ================= Phase A =================
    {
        u64 sa[8] = {0,0,0,0,0,0,0,0};
        #pragma unroll
        for (int d4 = 0; d4 < 16; d4++) {
            ulonglong2 k0 = kbU[d4*64 + (lane ^ d4)];
            #pragma unroll
            for (int qi = 0; qi < 8; qi++) {
                ulonglong2 q = qshU[(w + qi*4)*16 + d4];
                sa[qi] = ffma2(q.x, k0.x, sa[qi]);
                sa[qi] = ffma2(q.y, k0.y, sa[qi]);
            }
        }
        bool causal = (lane <= qb);
        #pragma unroll
        for (int qi = 0; qi < 8; qi++) {
            int r = w + qi*4;
            float2 fa = u2f2(sa[qi]);
            float sc = (fa.x + fa.y) * SCALE;
            bool rowok = (r < nvalid);
            p_sh[r*32 + lane] = (causal && rowok) ? siluf(sc) : 0.f;

            unsigned sel;
            if (!rowok) {
                sel = 0u;
            } else if (qb < STOP) {
                sel = (1u << (qb + 1)) - 1u;
            } else {
                unsigned ub = __float_as_uint(sc);
                unsigned u = ((int)ub < 0) ? ~ub : (ub | 0x80000000u);
                if (!causal) u = 0u;
                unsigned T = 0u;
                #pragma unroll
                for (int bit = 31; bit >= 0; --bit) {
                    unsigned cand = T | (1u << bit);
                    unsigned bal = __ballot_sync(0xffffffffu, u >= cand);
                    if (__popc(bal) >= STOP) T = cand;
                }
                unsigned gt = __ballot_sync(0xffffffffu, u > T);
                unsigned eq = __ballot_sync(0xffffffffu, u == T);
                int need = STOP - __popc(gt);
                bool take = ((eq >> lane) & 1u) &&
                            (__popc(eq & ((1u << lane) - 1u)) < need);
                unsigned eqt = __ballot_sync(0xffffffffu, take);
                sel = gt | eqt;
            }
            mysel[qi] = sel;
        }
        __syncwarp();
        unsigned wsel0 = 0;
        #pragma unroll
        for (int qi = 0; qi < 8; qi++) wsel0 |= mysel[qi];
        if (lane == 0) atomicOr(&unionm, wsel0);

        // compressed PV (keys 0..qb)
        int j4hi = qb >> 2;
        for (int j4 = 0; j4 <= j4hi; j4++) {
            u64 v[4];
            #pragma unroll
            for (int jj = 0; jj < 4; jj++) v[jj] = vbU[(j4*4 + jj)*32 + lane];
            #pragma unroll
            for (int qi = 0; qi < 8; qi++) {
                float4 pb = p4[(w + qi*4)*8 + j4];
                accC[qi] = ffma2(dup2(pb.x), v[0], accC[qi]);
                accC[qi] = ffma2(dup2(pb.y), v[1], accC[qi]);
                accC[qi] = ffma2(dup2(pb.z), v[2], accC[qi]);
                accC[qi] = ffma2(dup2(pb.w), v[3], accC[qi]);
            }
        }
    }
    unsigned wsel = 0;
    #pragma unroll
    for (int qi = 0; qi < 8; qi++) wsel |= mysel[qi];
    __syncthreads();
    unsigned um = unionm;
    if (tid == 0) {
        int c = 0;
        for (int kb = 0; kb <= qb; kb++)
            if ((um >> kb) & 1u) list[c++] = kb;
        lcnt = c;
    }
    __syncthreads();
    int cnt = lcnt;

    // ================= Phase B: paired 64-key tiles =================
    for (int it = 0; it < cnt; it += 2) {
        int kb0 = list[it];
        bool has1 = (it + 1 < cnt);
        int kb1 = has1 ? list[it + 1] : kb0;
        #pragma unroll
        for (int i = tid; i < 512; i += 128) {
            int row = i >> 4, c4 = i & 15;
            int g0 = ((b*Nc + kb0*BSc + row)*Hc + h)*Dc;
            int g1 = ((b*Nc + kb1*BSc + row)*Hc + h)*Dc;
            kb4[c4*64 + (row ^ c4)]        = ((const float4*)(pk + g0))[c4];
            kb4[c4*64 + ((row + 32) ^ c4)] = ((const float4*)(pk + g1))[c4];
            vb4[row*16 + c4]        = ((const float4*)(pvv + g0))[c4];
            vb4[(row + 32)*16 + c4] = ((const float4*)(pvv + g1))[c4];
        }
        __syncthreads();

        bool need0 = (wsel >> kb0) & 1u;
        bool need1 = has1 && ((wsel >> kb1) & 1u);
        if (need0 | need1) {
            u64 s0[8] = {0,0,0,0,0,0,0,0}, s1[8] = {0,0,0,0,0,0,0,0};
            #pragma unroll
            for (int d4 = 0; d4 < 16; d4++) {
                ulonglong2 k0 = kbU[d4*64 + (lane ^ d4)];
                ulonglong2 k1 = kbU[d4*64 + ((lane + 32) ^ d4)];
                #pragma unroll
                for (int qi = 0; qi < 8; qi++) {
                    ulonglong2 q = qshU[(w + qi*4)*16 + d4];
                    s0[qi] = ffma2(q.x, k0.x, s0[qi]);
                    s0[qi] = ffma2(q.y, k0.y, s0[qi]);
                    s1[qi] = ffma2(q.x, k1.x, s1[qi]);
                    s1[qi] = ffma2(q.y, k1.y, s1[qi]);
                }
            }
            // ---- tile 0 ----
            if (need0) {
                #pragma unroll
                for (int qi = 0; qi < 8; qi++) {
                    int r = w + qi*4;
                    int jmax = (kb0 == qb) ? r : 31;
                    bool u0 = ((mysel[qi] >> kb0) & 1u) && (lane <= jmax);
                    float2 f0 = u2f2(s0[qi]);
                    p_sh[r*32 + lane] = u0 ? siluf((f0.x + f0.y)*SCALE) : 0.f;
                }
                __syncwarp();
                #pragma unroll
                for (int j4 = 0; j4 < 8; j4++) {
                    u64 v[4];
                    #pragma unroll
                    for (int jj = 0; jj < 4; jj++) v[jj] = vbU[(j4*4 + jj)*32 + lane];
                    #pragma unroll
                    for (int qi = 0; qi < 8; qi++) {
                        float4 pb = p4[(w + qi*4)*8 + j4];
                        accS[qi] = ffma2(dup2(pb.x), v[0], accS[qi]);
                        accS[qi] = ffma2(dup2(pb.y), v[1], accS[qi]);
                        accS[qi] = ffma2(dup2(pb.z), v[2], accS[qi]);
                        accS[qi] = ffma2(dup2(pb.w), v[3], accS[qi]);
                    }
                }
                __syncwarp();
            }
            // ---- tile 1 ----
            if (need1) {
                #pragma unroll
                for (int qi = 0; qi < 8; qi++) {
                    int r = w + qi*4;
                    int jmax = (kb1 == qb) ? r : 31;
                    bool u1 = ((mysel[qi] >> kb1) & 1u) && (lane <= jmax);
                    float2 f1 = u2f2(s1[qi]);
                    p_sh[r*32 + lane] = u1 ? siluf((f1.x + f1.y)*SCALE) : 0.f;
                }
                __syncwarp();
                #pragma unroll
                for (int j4 = 0; j4 < 8; j4++) {
                    u64 v[4];
                    #pragma unroll
                    for (int jj = 0; jj < 4; jj++) v[jj] = vbU[(32 + j4*4 + jj)*32 + lane];
                    #pragma unroll
                    for (int qi = 0; qi < 8; qi++) {
                        float4 pb = p4[(w + qi*4)*8 + j4];
                        accS[qi] = ffma2(dup2(pb.x), v[0], accS[qi]);
                        accS[qi] = ffma2(dup2(pb.y), v[1], accS[qi]);
                        accS[qi] = ffma2(dup2(pb.z), v[2], accS[qi]);
                        accS[qi] = ffma2(dup2(pb.w), v[3], accS[qi]);
                    }
                }
            }
        }
        __syncthreads();
    }

    // ================= Output + gates (epilogue) =================
    const float* qs = (const float*)qsh4;
    const float* gw = gate_w + h*Dc*3;
    #pragma unroll
    for (int qi = 0; qi < 8; qi++) {
        int r = w + qi*4;
        if (r >= nvalid) continue;   // warp-uniform
        float q0 = qs[r*64 + 2*lane], q1 = qs[r*64 + 2*lane + 1];
        float pg0 = q0*gw[(2*lane)*3 + 0] + q1*gw[(2*lane+1)*3 + 0];
        float pg1 = q0*gw[(2*lane)*3 + 1] + q1*gw[(2*lane+1)*3 + 1];
        #pragma unroll
        for (int off = 16; off > 0; off >>= 1) {
            pg0 += __shfl_xor_sync(0xffffffffu, pg0, off);
            pg1 += __shfl_xor_sync(0xffffffffu, pg1, off);
        }
        float gcv = 1.f / (1.f + __expf(-pg0));
        float gsv = 1.f / (1.f + __expf(-pg1));
        float2 c = u2f2(accC[qi]), s2 = u2f2(accS[qi]);
        int n = qb*BSc + r;
        int o = ((t0 + n)*Hc + h)*Dc;
        float2 o2;
        o2.x = c.x*gcv + s2.x*gsv;
        o2.y = c.y*gcv + s2.y*gsv;
        *((float2*)(out + o) + lane) = o2;
    }
}

extern "C" void kernel_launch(void* const* d_in, const int* in_sizes, int n_in,
                              void* d_out, int out_size) {
    const float* pq   = (const float*)d_in[4];
    const float* pk   = (const float*)d_in[5];
    const float* pv   = (const float*)d_in[6];
    const int*   xoff = (const int*)d_in[7];
    const float* gw   = (const float*)d_in[8];
    float* out = (float*)d_out;

    meanKV<<<Bc*NBc*Hc, 64>>>(pk, pv);
    dim3 grid(NBc, Hc, Bc);
    hstu_main<<<grid, 128>>>(pq, pk, pv, gw, xoff, out);
}